// round 7
// baseline (speedup 1.0000x reference)
#include <cuda_runtime.h>
#include <mma.h>
#include <math.h>

using namespace nvcuda;

#define DIMC   1024
#define BATCH  2
#define SEQ    2048
#define MTOT   (BATCH*SEQ)      /* 4096 rows */
#define NHEAD  16
#define HD     64
#define QSCALE 0.125f           /* 64^-0.5 */

/* ------------- scratch (no allocations allowed) ------------- */
__device__ float g_Q[MTOT * DIMC];
__device__ float g_K[MTOT * DIMC];
__device__ float g_V[MTOT * DIMC];
__device__ float g_OUT[MTOT * DIMC];
__device__ float g_H1[MTOT * DIMC];
__device__ float g_Mpart[8 * BATCH * NHEAD * HD * HD];  /* partial K^T V, 8 S-chunks */
__device__ float g_M[BATCH * NHEAD * HD * HD];

/* =========================================================================
 * TF32 wmma GEMM:  C[m,n] = epilogue( sum_k A[m,k]*B[n,k] + bias[n] )
 * A: [M,K] row-major, B: [N,K] row-major (i.e. C = A @ B^T)
 * SPLIT_A=1: A represented exactly as tf32_hi + tf32_lo (2 MMAs) for accuracy.
 * EPI: 0 = (acc+bias)*alpha ; 1 = gelu_exact(acc+bias) ; 2 = acc+bias+r1+r2
 * All our GEMMs: M=4096, N=1024, K=1024 (no bounds checks needed).
 * ========================================================================= */
#define BM 128
#define BN 128
#define BK 32
#define BKP 36          /* padded K stride in smem (mult of 4 for wmma ldm) */

template<int SPLIT_A, int EPI>
__global__ void __launch_bounds__(256)
gemm_tf32_kernel(const float* __restrict__ A, const float* __restrict__ B,
                 const float* __restrict__ bias, float* __restrict__ C,
                 int M, int N, int K, float alpha,
                 const float* __restrict__ r1, const float* __restrict__ r2)
{
    __shared__ float As[BM][BKP];
    __shared__ float Bs[BN][BKP];
    __shared__ float Ep[8][16][20];   /* per-warp epilogue staging */

    const int tid  = threadIdx.x;
    const int wid  = tid >> 5;
    const int lane = tid & 31;
    const int wm   = wid >> 2;   /* 0..1 : 64-row slice   */
    const int wn   = wid & 3;    /* 0..3 : 32-col slice   */
    const int m0   = blockIdx.y * BM;
    const int n0   = blockIdx.x * BN;

    wmma::fragment<wmma::accumulator, 16, 16, 8, float> acc[4][2];
#pragma unroll
    for (int i = 0; i < 4; i++)
#pragma unroll
        for (int j = 0; j < 2; j++) wmma::fill_fragment(acc[i][j], 0.0f);

    for (int kb = 0; kb < K; kb += BK) {
        /* cooperative loads: 128x32 floats each, float4-vectorized, coalesced */
#pragma unroll
        for (int p = 0; p < 4; p++) {
            int slot = tid + p * 256;          /* 0..1023 */
            int r = slot >> 3;                 /* 0..127  */
            int c = (slot & 7) * 4;            /* 0..28   */
            *(float4*)&As[r][c] = *(const float4*)(A + (size_t)(m0 + r) * K + kb + c);
            *(float4*)&Bs[r][c] = *(const float4*)(B + (size_t)(n0 + r) * K + kb + c);
        }
        __syncthreads();

#pragma unroll
        for (int ks = 0; ks < BK; ks += 8) {
            wmma::fragment<wmma::matrix_b, 16, 16, 8, wmma::precision::tf32, wmma::col_major> bf[2];
#pragma unroll
            for (int j = 0; j < 2; j++) {
                wmma::load_matrix_sync(bf[j], &Bs[wn * 32 + j * 16][ks], BKP);
#pragma unroll
                for (int e = 0; e < bf[j].num_elements; e++)
                    bf[j].x[e] = wmma::__float_to_tf32(bf[j].x[e]);
            }
#pragma unroll
            for (int i = 0; i < 4; i++) {
                wmma::fragment<wmma::matrix_a, 16, 16, 8, wmma::precision::tf32, wmma::row_major> af, al;
                wmma::load_matrix_sync(af, &As[wm * 64 + i * 16][ks], BKP);
                if (SPLIT_A) {
#pragma unroll
                    for (int e = 0; e < af.num_elements; e++) {
                        float v  = af.x[e];
                        float hi = wmma::__float_to_tf32(v);
                        af.x[e]  = hi;
                        al.x[e]  = wmma::__float_to_tf32(v - hi);
                    }
                } else {
#pragma unroll
                    for (int e = 0; e < af.num_elements; e++)
                        af.x[e] = wmma::__float_to_tf32(af.x[e]);
                }
#pragma unroll
                for (int j = 0; j < 2; j++) {
                    wmma::mma_sync(acc[i][j], af, bf[j], acc[i][j]);
                    if (SPLIT_A) wmma::mma_sync(acc[i][j], al, bf[j], acc[i][j]);
                }
            }
        }
        __syncthreads();
    }

    /* epilogue: stage each 16x16 frag through smem, apply op, vector store */
#pragma unroll
    for (int i = 0; i < 4; i++) {
#pragma unroll
        for (int j = 0; j < 2; j++) {
            wmma::store_matrix_sync(&Ep[wid][0][0], acc[i][j], 20, wmma::mem_row_major);
            __syncwarp();
            int r  = lane & 15;
            int cb = (lane >> 4) * 8;
            int gr = m0 + wm * 64 + i * 16 + r;
            int gc = n0 + wn * 32 + j * 16 + cb;
            size_t base = (size_t)gr * N + gc;
            float v[8];
#pragma unroll
            for (int q = 0; q < 8; q++) {
                float t = Ep[wid][r][cb + q] + bias[gc + q];
                if (EPI == 0)       t *= alpha;
                else if (EPI == 1)  t = 0.5f * t * (1.0f + erff(t * 0.70710678118654752f));
                else                t += r1[base + q] + r2[base + q];
                v[q] = t;
            }
            *(float4*)(C + base)     = make_float4(v[0], v[1], v[2], v[3]);
            *(float4*)(C + base + 4) = make_float4(v[4], v[5], v[6], v[7]);
            __syncwarp();
        }
    }
}

/* =========================================================================
 * Partial M = K_h^T V_h over an S-chunk of 256 rows (exact fp32)
 * grid (B*H = 32, chunks = 8), 256 threads; each thread owns 4x4 of 64x64
 * ========================================================================= */
__global__ void __launch_bounds__(256)
kv_m_kernel(const float* __restrict__ K, const float* __restrict__ V,
            float* __restrict__ Mp)
{
    __shared__ float Ks[16][68];
    __shared__ float Vs[16][68];

    const int bh = blockIdx.x;               /* b*16 + h */
    const int b  = bh >> 4, h = bh & 15;
    const int s0 = blockIdx.y * 256;
    const int tid = threadIdx.x;
    const int e0 = (tid >> 4) * 4;
    const int d0 = (tid & 15) * 4;

    float acc[4][4] = {};
    const int lr = tid >> 4;                 /* 0..15 load row  */
    const int lc = (tid & 15) * 4;           /* 0..60 load col  */

    for (int st = 0; st < 256; st += 16) {
        size_t gi = ((size_t)(b * SEQ + s0 + st + lr)) * DIMC + h * HD + lc;
        *(float4*)&Ks[lr][lc] = *(const float4*)(K + gi);
        *(float4*)&Vs[lr][lc] = *(const float4*)(V + gi);
        __syncthreads();
#pragma unroll
        for (int ss = 0; ss < 16; ss++) {
            float kv[4], vv[4];
#pragma unroll
            for (int i = 0; i < 4; i++) { kv[i] = Ks[ss][e0 + i]; vv[i] = Vs[ss][d0 + i]; }
#pragma unroll
            for (int i = 0; i < 4; i++)
#pragma unroll
                for (int jj = 0; jj < 4; jj++) acc[i][jj] += kv[i] * vv[jj];
        }
        __syncthreads();
    }

    float* mo = Mp + ((size_t)blockIdx.y * 32 + bh) * (HD * HD);
#pragma unroll
    for (int i = 0; i < 4; i++)
#pragma unroll
        for (int jj = 0; jj < 4; jj++)
            mo[(e0 + i) * HD + d0 + jj] = acc[i][jj];
}

/* deterministic reduction of the 8 S-chunk partials */
__global__ void reduce_m_kernel(const float* __restrict__ Mp, float* __restrict__ Mo)
{
    int i = blockIdx.x * 256 + threadIdx.x;   /* 0 .. 32*4096-1 */
    float s = 0.0f;
#pragma unroll
    for (int p = 0; p < 8; p++) s += Mp[(size_t)p * 32 * HD * HD + i];
    Mo[i] = s;
}

/* =========================================================================
 * OUT[s, h*64+d] = sum_e Q[s, h*64+e] * M_h[e,d]  (exact fp32)
 * grid (B*H = 32, S/64 = 32), 256 threads; 64x64 output tile per block
 * ========================================================================= */
__global__ void __launch_bounds__(256)
qm_kernel(const float* __restrict__ Q, const float* __restrict__ Mi,
          float* __restrict__ O)
{
    __shared__ float Qs[64][68];
    __shared__ float Ms[64][68];

    const int bh = blockIdx.x;
    const int b  = bh >> 4, h = bh & 15;
    const int s0 = blockIdx.y * 64;
    const int tid = threadIdx.x;

#pragma unroll
    for (int p = 0; p < 4; p++) {
        int slot = tid + p * 256;             /* 0..1023 */
        int r = slot >> 4;                    /* 0..63   */
        int c = (slot & 15) * 4;              /* 0..60   */
        *(float4*)&Qs[r][c] = *(const float4*)(Q + ((size_t)(b * SEQ + s0 + r)) * DIMC + h * HD + c);
        *(float4*)&Ms[r][c] = *(const float4*)(Mi + (size_t)bh * HD * HD + r * HD + c);
    }
    __syncthreads();

    const int r0 = (tid >> 4) * 4;
    const int c0 = (tid & 15) * 4;
    float acc[4][4] = {};
#pragma unroll
    for (int k = 0; k < 64; k++) {
        float qv[4], mv[4];
#pragma unroll
        for (int i = 0; i < 4; i++) qv[i] = Qs[r0 + i][k];
#pragma unroll
        for (int jj = 0; jj < 4; jj++) mv[jj] = Ms[k][c0 + jj];
#pragma unroll
        for (int i = 0; i < 4; i++)
#pragma unroll
            for (int jj = 0; jj < 4; jj++) acc[i][jj] += qv[i] * mv[jj];
    }
#pragma unroll
    for (int i = 0; i < 4; i++)
#pragma unroll
        for (int jj = 0; jj < 4; jj++)
            O[((size_t)(b * SEQ + s0 + r0 + i)) * DIMC + h * HD + c0 + jj] = acc[i][jj];
}

/* ========================================================================= */
extern "C" void kernel_launch(void* const* d_in, const int* in_sizes, int n_in,
                              void* d_out, int out_size)
{
    const float* x  = (const float*)d_in[0];
    const float* Wq = (const float*)d_in[1];
    const float* bq = (const float*)d_in[2];
    const float* Wk = (const float*)d_in[3];
    const float* bk = (const float*)d_in[4];
    const float* Wv = (const float*)d_in[5];
    const float* bv = (const float*)d_in[6];
    const float* W1 = (const float*)d_in[7];
    const float* b1 = (const float*)d_in[8];
    const float* W2 = (const float*)d_in[9];
    const float* b2 = (const float*)d_in[10];
    float* Y = (float*)d_out;

    float *Q, *K, *V, *OUTP, *H1, *MP, *MM;
    cudaGetSymbolAddress((void**)&Q,    g_Q);
    cudaGetSymbolAddress((void**)&K,    g_K);
    cudaGetSymbolAddress((void**)&V,    g_V);
    cudaGetSymbolAddress((void**)&OUTP, g_OUT);
    cudaGetSymbolAddress((void**)&H1,   g_H1);
    cudaGetSymbolAddress((void**)&MP,   g_Mpart);
    cudaGetSymbolAddress((void**)&MM,   g_M);

    dim3 ggrid(DIMC / BN, MTOT / BM);   /* (8, 32) */
    dim3 gblk(256);

    /* Q,K,V projections: split-A tf32 (high accuracy), Q scaled by 1/sqrt(hd) */
    gemm_tf32_kernel<1, 0><<<ggrid, gblk>>>(x, Wq, bq, Q, MTOT, DIMC, DIMC, QSCALE, nullptr, nullptr);
    gemm_tf32_kernel<1, 0><<<ggrid, gblk>>>(x, Wk, bk, K, MTOT, DIMC, DIMC, 1.0f,   nullptr, nullptr);
    gemm_tf32_kernel<1, 0><<<ggrid, gblk>>>(x, Wv, bv, V, MTOT, DIMC, DIMC, 1.0f,   nullptr, nullptr);

    /* attention collapsed: out = Q @ (K^T V) per head */
    kv_m_kernel<<<dim3(32, 8), 256>>>(K, V, MP);
    reduce_m_kernel<<<(32 * HD * HD) / 256, 256>>>(MP, MM);
    qm_kernel<<<dim3(32, SEQ / 64), 256>>>(Q, MM, OUTP);

    /* MLP: h = gelu(OUT @ W1^T + b1); Y = x + OUT + (h @ W2^T + b2) */
    gemm_tf32_kernel<0, 1><<<ggrid, gblk>>>(OUTP, W1, b1, H1, MTOT, DIMC, DIMC, 1.0f, nullptr, nullptr);
    gemm_tf32_kernel<0, 2><<<ggrid, gblk>>>(H1, W2, b2, Y,  MTOT, DIMC, DIMC, 1.0f, x, OUTP);
}

// round 9
// speedup vs baseline: 2.2996x; 2.2996x over previous
#include <cuda_runtime.h>
#include <cuda_bf16.h>
#include <math.h>
#include <stdint.h>

#define DIMC   1024
#define BATCH  2
#define SEQ    2048
#define MTOT   (BATCH*SEQ)      /* 4096 rows */
#define NHEAD  16
#define HD     64
#define QSCALE 0.125f           /* 64^-0.5 */

/* ------------------- scratch (allocations forbidden) ------------------- */
__device__ float g_Q  [MTOT * DIMC];
__device__ float g_K  [MTOT * DIMC];
__device__ float g_V  [MTOT * DIMC];
__device__ float g_OUT[MTOT * DIMC];
__device__ float g_H1 [MTOT * DIMC];
__device__ float g_Mpart[16 * BATCH * NHEAD * HD * HD];
__device__ float g_M  [BATCH * NHEAD * HD * HD];

/* bf16 split operands */
__device__ __nv_bfloat16 g_xh [MTOT * DIMC], g_xl [MTOT * DIMC];
__device__ __nv_bfloat16 g_oh [MTOT * DIMC], g_ol [MTOT * DIMC];
__device__ __nv_bfloat16 g_hh [MTOT * DIMC], g_hl [MTOT * DIMC];
__device__ __nv_bfloat16 g_wqh[DIMC * DIMC], g_wql[DIMC * DIMC];
__device__ __nv_bfloat16 g_wkh[DIMC * DIMC], g_wkl[DIMC * DIMC];
__device__ __nv_bfloat16 g_wvh[DIMC * DIMC], g_wvl[DIMC * DIMC];
__device__ __nv_bfloat16 g_w1h[DIMC * DIMC], g_w1l[DIMC * DIMC];
__device__ __nv_bfloat16 g_w2h[DIMC * DIMC], g_w2l[DIMC * DIMC];

/* ============================ asm helpers =============================== */
__device__ __forceinline__ uint32_t smem_u32(const void* p) {
    uint32_t a;
    asm("{ .reg .u64 t; cvta.to.shared.u64 t, %1; cvt.u32.u64 %0, t; }"
        : "=r"(a) : "l"(p));
    return a;
}
#define CP_ASYNC16(saddr, gptr) \
    asm volatile("cp.async.cg.shared.global [%0], [%1], 16;" \
                 :: "r"(saddr), "l"(gptr) : "memory")
#define CP_COMMIT()  asm volatile("cp.async.commit_group;" ::: "memory")
#define CP_WAIT(N)   asm volatile("cp.async.wait_group %0;" :: "n"(N) : "memory")

__device__ __forceinline__ void ldsm_x4(uint32_t& r0, uint32_t& r1,
                                        uint32_t& r2, uint32_t& r3, uint32_t addr) {
    asm volatile("ldmatrix.sync.aligned.m8n8.x4.shared.b16 {%0,%1,%2,%3}, [%4];"
                 : "=r"(r0), "=r"(r1), "=r"(r2), "=r"(r3) : "r"(addr));
}
__device__ __forceinline__ void mma_bf16(float* c, const uint32_t* a,
                                         uint32_t b0, uint32_t b1) {
    asm volatile(
        "mma.sync.aligned.m16n8k16.row.col.f32.bf16.bf16.f32 "
        "{%0,%1,%2,%3},{%4,%5,%6,%7},{%8,%9},{%0,%1,%2,%3};"
        : "+f"(c[0]), "+f"(c[1]), "+f"(c[2]), "+f"(c[3])
        : "r"(a[0]), "r"(a[1]), "r"(a[2]), "r"(a[3]), "r"(b0), "r"(b1));
}

/* =========================================================================
 * bf16x3 GEMM (mma.sync.m16n8k16):
 *   C[m,n] = epi( sum_k A[m,k]*B[n,k] + bias[n] )
 *   A ~ Ah+Al, B ~ Bh+Bl (bf16).  acc += AhBh + AhBl + AlBh  (fp32)
 * Tile 128x128, BK=32, cp.async double buffer, 256 threads, 2 CTAs/SM.
 * smem rows padded to 80B (bank-conflict-free ldmatrix/lds).
 * EPI: 0 = (acc+bias)*alpha ; 1 = gelu_exact ; 2 = acc+bias+r1+r2
 * ========================================================================= */
#define TM 128
#define TN 128
#define BK 32
#define NCH (DIMC / BK)            /* 32 k-chunks */
#define PADB 80                    /* bytes per smem row (32 bf16 + pad) */
#define TILE_B (128 * PADB)        /* 10240 */
#define STAGE_B (4 * TILE_B)       /* Ah, Al, Bh, Bl */
#define GSMEM_DYN (2 * STAGE_B)    /* 81920 */

template<int EPI>
__global__ void __launch_bounds__(256, 2)
gemm_bf16x3(const __nv_bfloat16* __restrict__ Ah, const __nv_bfloat16* __restrict__ Al,
            const __nv_bfloat16* __restrict__ Bh, const __nv_bfloat16* __restrict__ Bl,
            const float* __restrict__ bias, float* __restrict__ C,
            float alpha, const float* __restrict__ r1, const float* __restrict__ r2)
{
    extern __shared__ char smem[];
    const uint32_t sbase = smem_u32(smem);

    const int tid  = threadIdx.x;
    const int wid  = tid >> 5;
    const int lane = tid & 31;
    const int wm   = wid >> 2;     /* 0..1  -> 64-row slice  */
    const int wn   = wid & 3;      /* 0..3  -> 32-col slice  */
    const int g    = lane >> 2;    /* group 0..7 */
    const int t    = lane & 3;
    const int m0   = blockIdx.y * TM;
    const int n0   = blockIdx.x * TN;

    const char* srcs[4];
    srcs[0] = (const char*)(Ah + (size_t)m0 * DIMC);
    srcs[1] = (const char*)(Al + (size_t)m0 * DIMC);
    srcs[2] = (const char*)(Bh + (size_t)n0 * DIMC);
    srcs[3] = (const char*)(Bl + (size_t)n0 * DIMC);

    /* per-thread cp.async mapping: 8 x 16B chunks per stage */
    int cid[8], crow[8], ccol[8];
#pragma unroll
    for (int it = 0; it < 8; it++) {
        int id = tid + it * 256;           /* 0..2047 */
        cid[it]  = id >> 9;                /* tile 0..3     */
        crow[it] = (id >> 2) & 127;        /* row 0..127    */
        ccol[it] = id & 3;                 /* 16B chunk 0..3 */
    }

    auto prefetch = [&](int ch, int buf) {
        const uint32_t sb = sbase + buf * STAGE_B;
#pragma unroll
        for (int it = 0; it < 8; it++) {
            const char* gp = srcs[cid[it]] + (size_t)crow[it] * (DIMC * 2)
                           + ch * (BK * 2) + ccol[it] * 16;
            uint32_t sa = sb + cid[it] * TILE_B + crow[it] * PADB + ccol[it] * 16;
            CP_ASYNC16(sa, gp);
        }
        CP_COMMIT();
    };

    float acc[4][4][4];
#pragma unroll
    for (int i = 0; i < 4; i++)
#pragma unroll
        for (int j = 0; j < 4; j++)
#pragma unroll
            for (int q = 0; q < 4; q++) acc[i][j][q] = 0.0f;

    prefetch(0, 0);

    /* ldmatrix lane address offset: row (lane&15), col-half (lane>>4) */
    const uint32_t lm_off = (uint32_t)(lane & 15) * PADB + (uint32_t)(lane >> 4) * 16;

    for (int ch = 0; ch < NCH; ch++) {
        const int buf = ch & 1;
        if (ch + 1 < NCH) { prefetch(ch + 1, buf ^ 1); CP_WAIT(1); }
        else              { CP_WAIT(0); }
        __syncthreads();

        const uint32_t sb   = sbase + buf * STAGE_B;
        const uint32_t aht  = sb;
        const uint32_t alt  = sb + TILE_B;
        const uint32_t bht  = sb + 2 * TILE_B;
        const uint32_t blt  = sb + 3 * TILE_B;

#pragma unroll
        for (int ks = 0; ks < 2; ks++) {          /* two k16 steps per BK=32 */
            /* B fragments: b0 @ k=2t, b1 @ k=2t+8 (bytes +16) */
            uint32_t bh[4][2], bl[4][2];
#pragma unroll
            for (int j = 0; j < 4; j++) {
                uint32_t nrow = (uint32_t)(wn * 32 + j * 8 + g) * PADB + ks * 32 + t * 4;
                asm volatile("ld.shared.b32 %0, [%1];" : "=r"(bh[j][0]) : "r"(bht + nrow));
                asm volatile("ld.shared.b32 %0, [%1];" : "=r"(bh[j][1]) : "r"(bht + nrow + 16));
                asm volatile("ld.shared.b32 %0, [%1];" : "=r"(bl[j][0]) : "r"(blt + nrow));
                asm volatile("ld.shared.b32 %0, [%1];" : "=r"(bl[j][1]) : "r"(blt + nrow + 16));
            }
#pragma unroll
            for (int i = 0; i < 4; i++) {
                uint32_t arow = (uint32_t)(wm * 64 + i * 16) * PADB + lm_off + ks * 32;
                uint32_t ah[4], al[4];
                ldsm_x4(ah[0], ah[1], ah[2], ah[3], aht + arow);
                ldsm_x4(al[0], al[1], al[2], al[3], alt + arow);
#pragma unroll
                for (int j = 0; j < 4; j++) {
                    mma_bf16(acc[i][j], ah, bh[j][0], bh[j][1]);
                    mma_bf16(acc[i][j], ah, bl[j][0], bl[j][1]);
                    mma_bf16(acc[i][j], al, bh[j][0], bh[j][1]);
                }
            }
        }
        __syncthreads();
    }

    /* ---------------- epilogue: register-resident ---------------- */
#pragma unroll
    for (int i = 0; i < 4; i++) {
        const int row0 = m0 + wm * 64 + i * 16 + g;
#pragma unroll
        for (int j = 0; j < 4; j++) {
            const int col = n0 + wn * 32 + j * 8 + 2 * t;
            float2 b2 = *(const float2*)(bias + col);
            float v[4] = { acc[i][j][0] + b2.x, acc[i][j][1] + b2.y,
                           acc[i][j][2] + b2.x, acc[i][j][3] + b2.y };
            size_t p0 = (size_t)row0 * DIMC + col;
            size_t p1 = (size_t)(row0 + 8) * DIMC + col;
            if (EPI == 0) {
#pragma unroll
                for (int q = 0; q < 4; q++) v[q] *= alpha;
            } else if (EPI == 1) {
#pragma unroll
                for (int q = 0; q < 4; q++)
                    v[q] = 0.5f * v[q] * (1.0f + erff(v[q] * 0.70710678118654752f));
            } else {
                float2 x0 = *(const float2*)(r1 + p0), o0 = *(const float2*)(r2 + p0);
                float2 x1 = *(const float2*)(r1 + p1), o1 = *(const float2*)(r2 + p1);
                v[0] += x0.x + o0.x; v[1] += x0.y + o0.y;
                v[2] += x1.x + o1.x; v[3] += x1.y + o1.y;
            }
            *(float2*)(C + p0) = make_float2(v[0], v[1]);
            *(float2*)(C + p1) = make_float2(v[2], v[3]);
        }
    }
}

/* ================== fp32 -> bf16 (hi, lo) split ========================= */
__global__ void split_kernel(const float* __restrict__ in,
                             __nv_bfloat16* __restrict__ hi,
                             __nv_bfloat16* __restrict__ lo, int n)
{
    int i = (blockIdx.x * 256 + threadIdx.x) * 4;
    if (i >= n) return;
    float4 v = *(const float4*)(in + i);
    __nv_bfloat16 h[4], l[4];
    float f[4] = {v.x, v.y, v.z, v.w};
#pragma unroll
    for (int k = 0; k < 4; k++) {
        h[k] = __float2bfloat16(f[k]);
        l[k] = __float2bfloat16(f[k] - __bfloat162float(h[k]));
    }
    ushort4 hv, lv;
    hv.x = *(unsigned short*)&h[0]; hv.y = *(unsigned short*)&h[1];
    hv.z = *(unsigned short*)&h[2]; hv.w = *(unsigned short*)&h[3];
    lv.x = *(unsigned short*)&l[0]; lv.y = *(unsigned short*)&l[1];
    lv.z = *(unsigned short*)&l[2]; lv.w = *(unsigned short*)&l[3];
    *(ushort4*)(hi + i) = hv;
    *(ushort4*)(lo + i) = lv;
}

/* =========================================================================
 * Attention middle (exact fp32):  M_h = K_h^T V_h ;  OUT = Q_h @ M_h
 * ========================================================================= */
__global__ void __launch_bounds__(256)
kv_m_kernel(const float* __restrict__ K, const float* __restrict__ V,
            float* __restrict__ Mp)
{
    __shared__ float Ks[16][68];
    __shared__ float Vs[16][68];

    const int bh = blockIdx.x;               /* b*16 + h */
    const int b  = bh >> 4, h = bh & 15;
    const int s0 = blockIdx.y * 128;
    const int tid = threadIdx.x;
    const int e0 = (tid >> 4) * 4;
    const int d0 = (tid & 15) * 4;

    float acc[4][4] = {};
    const int lr = tid >> 4;
    const int lc = (tid & 15) * 4;

    for (int st = 0; st < 128; st += 16) {
        size_t gi = ((size_t)(b * SEQ + s0 + st + lr)) * DIMC + h * HD + lc;
        *(float4*)&Ks[lr][lc] = *(const float4*)(K + gi);
        *(float4*)&Vs[lr][lc] = *(const float4*)(V + gi);
        __syncthreads();
#pragma unroll
        for (int ss = 0; ss < 16; ss++) {
            float kv[4], vv[4];
#pragma unroll
            for (int i = 0; i < 4; i++) { kv[i] = Ks[ss][e0 + i]; vv[i] = Vs[ss][d0 + i]; }
#pragma unroll
            for (int i = 0; i < 4; i++)
#pragma unroll
                for (int jj = 0; jj < 4; jj++) acc[i][jj] += kv[i] * vv[jj];
        }
        __syncthreads();
    }

    float* mo = Mp + ((size_t)blockIdx.y * 32 + bh) * (HD * HD);
#pragma unroll
    for (int i = 0; i < 4; i++)
#pragma unroll
        for (int jj = 0; jj < 4; jj++)
            mo[(e0 + i) * HD + d0 + jj] = acc[i][jj];
}

__global__ void reduce_m_kernel(const float* __restrict__ Mp, float* __restrict__ Mo)
{
    int i = blockIdx.x * 256 + threadIdx.x;   /* 0 .. 32*4096-1 */
    float s = 0.0f;
#pragma unroll
    for (int p = 0; p < 16; p++) s += Mp[(size_t)p * 32 * HD * HD + i];
    Mo[i] = s;
}

__global__ void __launch_bounds__(256)
qm_kernel(const float* __restrict__ Q, const float* __restrict__ Mi,
          float* __restrict__ O)
{
    __shared__ float Qs[64][68];
    __shared__ float Ms[64][68];

    const int bh = blockIdx.x;
    const int b  = bh >> 4, h = bh & 15;
    const int s0 = blockIdx.y * 64;
    const int tid = threadIdx.x;

#pragma unroll
    for (int p = 0; p < 4; p++) {
        int slot = tid + p * 256;
        int r = slot >> 4;
        int c = (slot & 15) * 4;
        *(float4*)&Qs[r][c] = *(const float4*)(Q + ((size_t)(b * SEQ + s0 + r)) * DIMC + h * HD + c);
        *(float4*)&Ms[r][c] = *(const float4*)(Mi + (size_t)bh * HD * HD + r * HD + c);
    }
    __syncthreads();

    const int r0 = (tid >> 4) * 4;
    const int c0 = (tid & 15) * 4;
    float acc[4][4] = {};
#pragma unroll
    for (int k = 0; k < 64; k++) {
        float qv[4], mv[4];
#pragma unroll
        for (int i = 0; i < 4; i++) qv[i] = Qs[r0 + i][k];
#pragma unroll
        for (int jj = 0; jj < 4; jj++) mv[jj] = Ms[k][c0 + jj];
#pragma unroll
        for (int i = 0; i < 4; i++)
#pragma unroll
            for (int jj = 0; jj < 4; jj++) acc[i][jj] += qv[i] * mv[jj];
    }
#pragma unroll
    for (int i = 0; i < 4; i++)
#pragma unroll
        for (int jj = 0; jj < 4; jj++)
            O[((size_t)(b * SEQ + s0 + r0 + i)) * DIMC + h * HD + c0 + jj] = acc[i][jj];
}

/* ========================================================================= */
extern "C" void kernel_launch(void* const* d_in, const int* in_sizes, int n_in,
                              void* d_out, int out_size)
{
    const float* x  = (const float*)d_in[0];
    const float* Wq = (const float*)d_in[1];
    const float* bq = (const float*)d_in[2];
    const float* Wk = (const float*)d_in[3];
    const float* bk = (const float*)d_in[4];
    const float* Wv = (const float*)d_in[5];
    const float* bv = (const float*)d_in[6];
    const float* W1 = (const float*)d_in[7];
    const float* b1 = (const float*)d_in[8];
    const float* W2 = (const float*)d_in[9];
    const float* b2 = (const float*)d_in[10];
    float* Y = (float*)d_out;

    float *Q, *K, *V, *OUTP, *H1, *MP, *MM;
    cudaGetSymbolAddress((void**)&Q,    g_Q);
    cudaGetSymbolAddress((void**)&K,    g_K);
    cudaGetSymbolAddress((void**)&V,    g_V);
    cudaGetSymbolAddress((void**)&OUTP, g_OUT);
    cudaGetSymbolAddress((void**)&H1,   g_H1);
    cudaGetSymbolAddress((void**)&MP,   g_Mpart);
    cudaGetSymbolAddress((void**)&MM,   g_M);

    __nv_bfloat16 *xh, *xl, *oh, *ol, *hh, *hl;
    __nv_bfloat16 *wqh, *wql, *wkh, *wkl, *wvh, *wvl, *w1h, *w1l, *w2h, *w2l;
    cudaGetSymbolAddress((void**)&xh,  g_xh);  cudaGetSymbolAddress((void**)&xl,  g_xl);
    cudaGetSymbolAddress((void**)&oh,  g_oh);  cudaGetSymbolAddress((void**)&ol,  g_ol);
    cudaGetSymbolAddress((void**)&hh,  g_hh);  cudaGetSymbolAddress((void**)&hl,  g_hl);
    cudaGetSymbolAddress((void**)&wqh, g_wqh); cudaGetSymbolAddress((void**)&wql, g_wql);
    cudaGetSymbolAddress((void**)&wkh, g_wkh); cudaGetSymbolAddress((void**)&wkl, g_wkl);
    cudaGetSymbolAddress((void**)&wvh, g_wvh); cudaGetSymbolAddress((void**)&wvl, g_wvl);
    cudaGetSymbolAddress((void**)&w1h, g_w1h); cudaGetSymbolAddress((void**)&w1l, g_w1l);
    cudaGetSymbolAddress((void**)&w2h, g_w2h); cudaGetSymbolAddress((void**)&w2l, g_w2l);

    cudaFuncSetAttribute(gemm_bf16x3<0>, cudaFuncAttributeMaxDynamicSharedMemorySize, GSMEM_DYN);
    cudaFuncSetAttribute(gemm_bf16x3<1>, cudaFuncAttributeMaxDynamicSharedMemorySize, GSMEM_DYN);
    cudaFuncSetAttribute(gemm_bf16x3<2>, cudaFuncAttributeMaxDynamicSharedMemorySize, GSMEM_DYN);

    const int NX = MTOT * DIMC;   /* 4.19M */
    const int NW = DIMC * DIMC;   /* 1.05M */
    dim3 sgx((NX / 4 + 255) / 256), sgw((NW / 4 + 255) / 256);

    /* bf16 splits of activations & weights */
    split_kernel<<<sgx, 256>>>(x,  xh,  xl,  NX);
    split_kernel<<<sgw, 256>>>(Wq, wqh, wql, NW);
    split_kernel<<<sgw, 256>>>(Wk, wkh, wkl, NW);
    split_kernel<<<sgw, 256>>>(Wv, wvh, wvl, NW);
    split_kernel<<<sgw, 256>>>(W1, w1h, w1l, NW);
    split_kernel<<<sgw, 256>>>(W2, w2h, w2l, NW);

    dim3 ggrid(DIMC / TN, MTOT / TM);   /* (8, 32) */

    /* projections (bf16x3 on HMMA tensor cores) */
    gemm_bf16x3<0><<<ggrid, 256, GSMEM_DYN>>>(xh, xl, wqh, wql, bq, Q, QSCALE, nullptr, nullptr);
    gemm_bf16x3<0><<<ggrid, 256, GSMEM_DYN>>>(xh, xl, wkh, wkl, bk, K, 1.0f,   nullptr, nullptr);
    gemm_bf16x3<0><<<ggrid, 256, GSMEM_DYN>>>(xh, xl, wvh, wvl, bv, V, 1.0f,   nullptr, nullptr);

    /* attention collapsed: out = Q @ (K^T V) per head, exact fp32 */
    kv_m_kernel<<<dim3(32, 16), 256>>>(K, V, MP);
    reduce_m_kernel<<<(32 * HD * HD) / 256, 256>>>(MP, MM);
    qm_kernel<<<dim3(32, SEQ / 64), 256>>>(Q, MM, OUTP);

    /* MLP: h = gelu(OUT @ W1^T + b1); Y = x + OUT + (h @ W2^T + b2) */
    split_kernel<<<sgx, 256>>>(OUTP, oh, ol, NX);
    gemm_bf16x3<1><<<ggrid, 256, GSMEM_DYN>>>(oh, ol, w1h, w1l, b1, H1, 1.0f, nullptr, nullptr);
    split_kernel<<<sgx, 256>>>(H1, hh, hl, NX);
    gemm_bf16x3<2><<<ggrid, 256, GSMEM_DYN>>>(hh, hl, w2h, w2l, b2, Y, 1.0f, x, OUTP);
}

// round 10
// speedup vs baseline: 2.3088x; 1.0040x over previous
#include <cuda_runtime.h>
#include <cuda_bf16.h>
#include <math.h>
#include <stdint.h>

#define DIMC   1024
#define BATCH  2
#define SEQ    2048
#define MTOT   (BATCH*SEQ)      /* 4096 rows */
#define NHEAD  16
#define HD     64
#define QSCALE 0.125f           /* 64^-0.5 */

/* ------------------- scratch (allocations forbidden) ------------------- */
__device__ float g_Q  [MTOT * DIMC];
__device__ float g_K  [MTOT * DIMC];
__device__ float g_V  [MTOT * DIMC];
__device__ float g_OUT[MTOT * DIMC];
__device__ float g_H1 [MTOT * DIMC];
__device__ float g_Mpart[16 * BATCH * NHEAD * HD * HD];
__device__ float g_M  [BATCH * NHEAD * HD * HD];

/* bf16 split operands */
__device__ __nv_bfloat16 g_xh [MTOT * DIMC], g_xl [MTOT * DIMC];
__device__ __nv_bfloat16 g_oh [MTOT * DIMC], g_ol [MTOT * DIMC];
__device__ __nv_bfloat16 g_hh [MTOT * DIMC], g_hl [MTOT * DIMC];
__device__ __nv_bfloat16 g_wqh[DIMC * DIMC], g_wql[DIMC * DIMC];
__device__ __nv_bfloat16 g_wkh[DIMC * DIMC], g_wkl[DIMC * DIMC];
__device__ __nv_bfloat16 g_wvh[DIMC * DIMC], g_wvl[DIMC * DIMC];
__device__ __nv_bfloat16 g_w1h[DIMC * DIMC], g_w1l[DIMC * DIMC];
__device__ __nv_bfloat16 g_w2h[DIMC * DIMC], g_w2l[DIMC * DIMC];

/* ============================ asm helpers =============================== */
__device__ __forceinline__ uint32_t smem_u32(const void* p) {
    uint32_t a;
    asm("{ .reg .u64 t; cvta.to.shared.u64 t, %1; cvt.u32.u64 %0, t; }"
        : "=r"(a) : "l"(p));
    return a;
}
#define CP_ASYNC16(saddr, gptr) \
    asm volatile("cp.async.cg.shared.global [%0], [%1], 16;" \
                 :: "r"(saddr), "l"(gptr) : "memory")
#define CP_COMMIT()  asm volatile("cp.async.commit_group;" ::: "memory")
#define CP_WAIT(N)   asm volatile("cp.async.wait_group %0;" :: "n"(N) : "memory")

__device__ __forceinline__ void ldsm_x4(uint32_t& r0, uint32_t& r1,
                                        uint32_t& r2, uint32_t& r3, uint32_t addr) {
    asm volatile("ldmatrix.sync.aligned.m8n8.x4.shared.b16 {%0,%1,%2,%3}, [%4];"
                 : "=r"(r0), "=r"(r1), "=r"(r2), "=r"(r3) : "r"(addr));
}
__device__ __forceinline__ void mma_bf16(float* c, const uint32_t* a,
                                         uint32_t b0, uint32_t b1) {
    asm volatile(
        "mma.sync.aligned.m16n8k16.row.col.f32.bf16.bf16.f32 "
        "{%0,%1,%2,%3},{%4,%5,%6,%7},{%8,%9},{%0,%1,%2,%3};"
        : "+f"(c[0]), "+f"(c[1]), "+f"(c[2]), "+f"(c[3])
        : "r"(a[0]), "r"(a[1]), "r"(a[2]), "r"(a[3]), "r"(b0), "r"(b1));
}

/* =========================================================================
 * bf16x3 GEMM (mma.sync.m16n8k16):
 *   C[m,n] = epi( sum_k A[m,k]*B[n,k] + bias[n] )
 *   A ~ Ah+Al, B ~ Bh+Bl (bf16).  acc += AhBh + AhBl + AlBh  (fp32)
 * Tile 128x128, BK=32, cp.async double buffer, 256 threads, 2 CTAs/SM.
 * smem rows padded to 80B (bank-conflict-free ldmatrix/lds).
 * EPI: 0 = (acc+bias)*alpha ; 1 = gelu_exact ; 2 = acc+bias+r1+r2
 * ========================================================================= */
#define TM 128
#define TN 128
#define BK 32
#define NCH (DIMC / BK)            /* 32 k-chunks */
#define PADB 80                    /* bytes per smem row (32 bf16 + pad) */
#define TILE_B (128 * PADB)        /* 10240 */
#define STAGE_B (4 * TILE_B)       /* Ah, Al, Bh, Bl */
#define GSMEM_DYN (2 * STAGE_B)    /* 81920 */

template<int EPI>
__global__ void __launch_bounds__(256, 2)
gemm_bf16x3(const __nv_bfloat16* __restrict__ Ah, const __nv_bfloat16* __restrict__ Al,
            const __nv_bfloat16* __restrict__ Bh, const __nv_bfloat16* __restrict__ Bl,
            const float* __restrict__ bias, float* __restrict__ C,
            float alpha, const float* __restrict__ r1, const float* __restrict__ r2)
{
    extern __shared__ char smem[];
    const uint32_t sbase = smem_u32(smem);

    const int tid  = threadIdx.x;
    const int wid  = tid >> 5;
    const int lane = tid & 31;
    const int wm   = wid >> 2;     /* 0..1  -> 64-row slice  */
    const int wn   = wid & 3;      /* 0..3  -> 32-col slice  */
    const int g    = lane >> 2;    /* group 0..7 */
    const int t    = lane & 3;
    const int m0   = blockIdx.y * TM;
    const int n0   = blockIdx.x * TN;

    const char* srcs[4];
    srcs[0] = (const char*)(Ah + (size_t)m0 * DIMC);
    srcs[1] = (const char*)(Al + (size_t)m0 * DIMC);
    srcs[2] = (const char*)(Bh + (size_t)n0 * DIMC);
    srcs[3] = (const char*)(Bl + (size_t)n0 * DIMC);

    /* per-thread cp.async mapping: 8 x 16B chunks per stage */
    int cid[8], crow[8], ccol[8];
#pragma unroll
    for (int it = 0; it < 8; it++) {
        int id = tid + it * 256;           /* 0..2047 */
        cid[it]  = id >> 9;                /* tile 0..3     */
        crow[it] = (id >> 2) & 127;        /* row 0..127    */
        ccol[it] = id & 3;                 /* 16B chunk 0..3 */
    }

    auto prefetch = [&](int ch, int buf) {
        const uint32_t sb = sbase + buf * STAGE_B;
#pragma unroll
        for (int it = 0; it < 8; it++) {
            const char* gp = srcs[cid[it]] + (size_t)crow[it] * (DIMC * 2)
                           + ch * (BK * 2) + ccol[it] * 16;
            uint32_t sa = sb + cid[it] * TILE_B + crow[it] * PADB + ccol[it] * 16;
            CP_ASYNC16(sa, gp);
        }
        CP_COMMIT();
    };

    float acc[4][4][4];
#pragma unroll
    for (int i = 0; i < 4; i++)
#pragma unroll
        for (int j = 0; j < 4; j++)
#pragma unroll
            for (int q = 0; q < 4; q++) acc[i][j][q] = 0.0f;

    prefetch(0, 0);

    /* ldmatrix lane address offset: row (lane&15), col-half (lane>>4) */
    const uint32_t lm_off = (uint32_t)(lane & 15) * PADB + (uint32_t)(lane >> 4) * 16;

    for (int ch = 0; ch < NCH; ch++) {
        const int buf = ch & 1;
        if (ch + 1 < NCH) { prefetch(ch + 1, buf ^ 1); CP_WAIT(1); }
        else              { CP_WAIT(0); }
        __syncthreads();

        const uint32_t sb   = sbase + buf * STAGE_B;
        const uint32_t aht  = sb;
        const uint32_t alt  = sb + TILE_B;
        const uint32_t bht  = sb + 2 * TILE_B;
        const uint32_t blt  = sb + 3 * TILE_B;

#pragma unroll
        for (int ks = 0; ks < 2; ks++) {          /* two k16 steps per BK=32 */
            /* B fragments: b0 @ k=2t, b1 @ k=2t+8 (bytes +16) */
            uint32_t bh[4][2], bl[4][2];
#pragma unroll
            for (int j = 0; j < 4; j++) {
                uint32_t nrow = (uint32_t)(wn * 32 + j * 8 + g) * PADB + ks * 32 + t * 4;
                asm volatile("ld.shared.b32 %0, [%1];" : "=r"(bh[j][0]) : "r"(bht + nrow));
                asm volatile("ld.shared.b32 %0, [%1];" : "=r"(bh[j][1]) : "r"(bht + nrow + 16));
                asm volatile("ld.shared.b32 %0, [%1];" : "=r"(bl[j][0]) : "r"(blt + nrow));
                asm volatile("ld.shared.b32 %0, [%1];" : "=r"(bl[j][1]) : "r"(blt + nrow + 16));
            }
#pragma unroll
            for (int i = 0; i < 4; i++) {
                uint32_t arow = (uint32_t)(wm * 64 + i * 16) * PADB + lm_off + ks * 32;
                uint32_t ah[4], al[4];
                ldsm_x4(ah[0], ah[1], ah[2], ah[3], aht + arow);
                ldsm_x4(al[0], al[1], al[2], al[3], alt + arow);
#pragma unroll
                for (int j = 0; j < 4; j++) {
                    mma_bf16(acc[i][j], ah, bh[j][0], bh[j][1]);
                    mma_bf16(acc[i][j], ah, bl[j][0], bl[j][1]);
                    mma_bf16(acc[i][j], al, bh[j][0], bh[j][1]);
                }
            }
        }
        __syncthreads();
    }

    /* ---------------- epilogue: register-resident ---------------- */
#pragma unroll
    for (int i = 0; i < 4; i++) {
        const int row0 = m0 + wm * 64 + i * 16 + g;
#pragma unroll
        for (int j = 0; j < 4; j++) {
            const int col = n0 + wn * 32 + j * 8 + 2 * t;
            float2 b2 = *(const float2*)(bias + col);
            float v[4] = { acc[i][j][0] + b2.x, acc[i][j][1] + b2.y,
                           acc[i][j][2] + b2.x, acc[i][j][3] + b2.y };
            size_t p0 = (size_t)row0 * DIMC + col;
            size_t p1 = (size_t)(row0 + 8) * DIMC + col;
            if (EPI == 0) {
#pragma unroll
                for (int q = 0; q < 4; q++) v[q] *= alpha;
            } else if (EPI == 1) {
#pragma unroll
                for (int q = 0; q < 4; q++)
                    v[q] = 0.5f * v[q] * (1.0f + erff(v[q] * 0.70710678118654752f));
            } else {
                float2 x0 = *(const float2*)(r1 + p0), o0 = *(const float2*)(r2 + p0);
                float2 x1 = *(const float2*)(r1 + p1), o1 = *(const float2*)(r2 + p1);
                v[0] += x0.x + o0.x; v[1] += x0.y + o0.y;
                v[2] += x1.x + o1.x; v[3] += x1.y + o1.y;
            }
            *(float2*)(C + p0) = make_float2(v[0], v[1]);
            *(float2*)(C + p1) = make_float2(v[2], v[3]);
        }
    }
}

/* ================== fp32 -> bf16 (hi, lo) split ========================= */
__global__ void split_kernel(const float* __restrict__ in,
                             __nv_bfloat16* __restrict__ hi,
                             __nv_bfloat16* __restrict__ lo, int n)
{
    int i = (blockIdx.x * 256 + threadIdx.x) * 4;
    if (i >= n) return;
    float4 v = *(const float4*)(in + i);
    __nv_bfloat16 h[4], l[4];
    float f[4] = {v.x, v.y, v.z, v.w};
#pragma unroll
    for (int k = 0; k < 4; k++) {
        h[k] = __float2bfloat16(f[k]);
        l[k] = __float2bfloat16(f[k] - __bfloat162float(h[k]));
    }
    ushort4 hv, lv;
    hv.x = *(unsigned short*)&h[0]; hv.y = *(unsigned short*)&h[1];
    hv.z = *(unsigned short*)&h[2]; hv.w = *(unsigned short*)&h[3];
    lv.x = *(unsigned short*)&l[0]; lv.y = *(unsigned short*)&l[1];
    lv.z = *(unsigned short*)&l[2]; lv.w = *(unsigned short*)&l[3];
    *(ushort4*)(hi + i) = hv;
    *(ushort4*)(lo + i) = lv;
}

/* =========================================================================
 * Attention middle (exact fp32):  M_h = K_h^T V_h ;  OUT = Q_h @ M_h
 * ========================================================================= */
__global__ void __launch_bounds__(256)
kv_m_kernel(const float* __restrict__ K, const float* __restrict__ V,
            float* __restrict__ Mp)
{
    __shared__ float Ks[16][68];
    __shared__ float Vs[16][68];

    const int bh = blockIdx.x;               /* b*16 + h */
    const int b  = bh >> 4, h = bh & 15;
    const int s0 = blockIdx.y * 128;
    const int tid = threadIdx.x;
    const int e0 = (tid >> 4) * 4;
    const int d0 = (tid & 15) * 4;

    float acc[4][4] = {};
    const int lr = tid >> 4;
    const int lc = (tid & 15) * 4;

    for (int st = 0; st < 128; st += 16) {
        size_t gi = ((size_t)(b * SEQ + s0 + st + lr)) * DIMC + h * HD + lc;
        *(float4*)&Ks[lr][lc] = *(const float4*)(K + gi);
        *(float4*)&Vs[lr][lc] = *(const float4*)(V + gi);
        __syncthreads();
#pragma unroll
        for (int ss = 0; ss < 16; ss++) {
            float kv[4], vv[4];
#pragma unroll
            for (int i = 0; i < 4; i++) { kv[i] = Ks[ss][e0 + i]; vv[i] = Vs[ss][d0 + i]; }
#pragma unroll
            for (int i = 0; i < 4; i++)
#pragma unroll
                for (int jj = 0; jj < 4; jj++) acc[i][jj] += kv[i] * vv[jj];
        }
        __syncthreads();
    }

    float* mo = Mp + ((size_t)blockIdx.y * 32 + bh) * (HD * HD);
#pragma unroll
    for (int i = 0; i < 4; i++)
#pragma unroll
        for (int jj = 0; jj < 4; jj++)
            mo[(e0 + i) * HD + d0 + jj] = acc[i][jj];
}

__global__ void reduce_m_kernel(const float* __restrict__ Mp, float* __restrict__ Mo)
{
    int i = blockIdx.x * 256 + threadIdx.x;   /* 0 .. 32*4096-1 */
    float s = 0.0f;
#pragma unroll
    for (int p = 0; p < 16; p++) s += Mp[(size_t)p * 32 * HD * HD + i];
    Mo[i] = s;
}

__global__ void __launch_bounds__(256)
qm_kernel(const float* __restrict__ Q, const float* __restrict__ Mi,
          float* __restrict__ O)
{
    __shared__ float Qs[64][68];
    __shared__ float Ms[64][68];

    const int bh = blockIdx.x;
    const int b  = bh >> 4, h = bh & 15;
    const int s0 = blockIdx.y * 64;
    const int tid = threadIdx.x;

#pragma unroll
    for (int p = 0; p < 4; p++) {
        int slot = tid + p * 256;
        int r = slot >> 4;
        int c = (slot & 15) * 4;
        *(float4*)&Qs[r][c] = *(const float4*)(Q + ((size_t)(b * SEQ + s0 + r)) * DIMC + h * HD + c);
        *(float4*)&Ms[r][c] = *(const float4*)(Mi + (size_t)bh * HD * HD + r * HD + c);
    }
    __syncthreads();

    const int r0 = (tid >> 4) * 4;
    const int c0 = (tid & 15) * 4;
    float acc[4][4] = {};
#pragma unroll
    for (int k = 0; k < 64; k++) {
        float qv[4], mv[4];
#pragma unroll
        for (int i = 0; i < 4; i++) qv[i] = Qs[r0 + i][k];
#pragma unroll
        for (int jj = 0; jj < 4; jj++) mv[jj] = Ms[k][c0 + jj];
#pragma unroll
        for (int i = 0; i < 4; i++)
#pragma unroll
            for (int jj = 0; jj < 4; jj++) acc[i][jj] += qv[i] * mv[jj];
    }
#pragma unroll
    for (int i = 0; i < 4; i++)
#pragma unroll
        for (int jj = 0; jj < 4; jj++)
            O[((size_t)(b * SEQ + s0 + r0 + i)) * DIMC + h * HD + c0 + jj] = acc[i][jj];
}

/* ========================================================================= */
extern "C" void kernel_launch(void* const* d_in, const int* in_sizes, int n_in,
                              void* d_out, int out_size)
{
    const float* x  = (const float*)d_in[0];
    const float* Wq = (const float*)d_in[1];
    const float* bq = (const float*)d_in[2];
    const float* Wk = (const float*)d_in[3];
    const float* bk = (const float*)d_in[4];
    const float* Wv = (const float*)d_in[5];
    const float* bv = (const float*)d_in[6];
    const float* W1 = (const float*)d_in[7];
    const float* b1 = (const float*)d_in[8];
    const float* W2 = (const float*)d_in[9];
    const float* b2 = (const float*)d_in[10];
    float* Y = (float*)d_out;

    float *Q, *K, *V, *OUTP, *H1, *MP, *MM;
    cudaGetSymbolAddress((void**)&Q,    g_Q);
    cudaGetSymbolAddress((void**)&K,    g_K);
    cudaGetSymbolAddress((void**)&V,    g_V);
    cudaGetSymbolAddress((void**)&OUTP, g_OUT);
    cudaGetSymbolAddress((void**)&H1,   g_H1);
    cudaGetSymbolAddress((void**)&MP,   g_Mpart);
    cudaGetSymbolAddress((void**)&MM,   g_M);

    __nv_bfloat16 *xh, *xl, *oh, *ol, *hh, *hl;
    __nv_bfloat16 *wqh, *wql, *wkh, *wkl, *wvh, *wvl, *w1h, *w1l, *w2h, *w2l;
    cudaGetSymbolAddress((void**)&xh,  g_xh);  cudaGetSymbolAddress((void**)&xl,  g_xl);
    cudaGetSymbolAddress((void**)&oh,  g_oh);  cudaGetSymbolAddress((void**)&ol,  g_ol);
    cudaGetSymbolAddress((void**)&hh,  g_hh);  cudaGetSymbolAddress((void**)&hl,  g_hl);
    cudaGetSymbolAddress((void**)&wqh, g_wqh); cudaGetSymbolAddress((void**)&wql, g_wql);
    cudaGetSymbolAddress((void**)&wkh, g_wkh); cudaGetSymbolAddress((void**)&wkl, g_wkl);
    cudaGetSymbolAddress((void**)&wvh, g_wvh); cudaGetSymbolAddress((void**)&wvl, g_wvl);
    cudaGetSymbolAddress((void**)&w1h, g_w1h); cudaGetSymbolAddress((void**)&w1l, g_w1l);
    cudaGetSymbolAddress((void**)&w2h, g_w2h); cudaGetSymbolAddress((void**)&w2l, g_w2l);

    cudaFuncSetAttribute(gemm_bf16x3<0>, cudaFuncAttributeMaxDynamicSharedMemorySize, GSMEM_DYN);
    cudaFuncSetAttribute(gemm_bf16x3<1>, cudaFuncAttributeMaxDynamicSharedMemorySize, GSMEM_DYN);
    cudaFuncSetAttribute(gemm_bf16x3<2>, cudaFuncAttributeMaxDynamicSharedMemorySize, GSMEM_DYN);

    const int NX = MTOT * DIMC;   /* 4.19M */
    const int NW = DIMC * DIMC;   /* 1.05M */
    dim3 sgx((NX / 4 + 255) / 256), sgw((NW / 4 + 255) / 256);

    /* bf16 splits of activations & weights */
    split_kernel<<<sgx, 256>>>(x,  xh,  xl,  NX);
    split_kernel<<<sgw, 256>>>(Wq, wqh, wql, NW);
    split_kernel<<<sgw, 256>>>(Wk, wkh, wkl, NW);
    split_kernel<<<sgw, 256>>>(Wv, wvh, wvl, NW);
    split_kernel<<<sgw, 256>>>(W1, w1h, w1l, NW);
    split_kernel<<<sgw, 256>>>(W2, w2h, w2l, NW);

    dim3 ggrid(DIMC / TN, MTOT / TM);   /* (8, 32) */

    /* projections (bf16x3 on HMMA tensor cores) */
    gemm_bf16x3<0><<<ggrid, 256, GSMEM_DYN>>>(xh, xl, wqh, wql, bq, Q, QSCALE, nullptr, nullptr);
    gemm_bf16x3<0><<<ggrid, 256, GSMEM_DYN>>>(xh, xl, wkh, wkl, bk, K, 1.0f,   nullptr, nullptr);
    gemm_bf16x3<0><<<ggrid, 256, GSMEM_DYN>>>(xh, xl, wvh, wvl, bv, V, 1.0f,   nullptr, nullptr);

    /* attention collapsed: out = Q @ (K^T V) per head, exact fp32 */
    kv_m_kernel<<<dim3(32, 16), 256>>>(K, V, MP);
    reduce_m_kernel<<<(32 * HD * HD) / 256, 256>>>(MP, MM);
    qm_kernel<<<dim3(32, SEQ / 64), 256>>>(Q, MM, OUTP);

    /* MLP: h = gelu(OUT @ W1^T + b1); Y = x + OUT + (h @ W2^T + b2) */
    split_kernel<<<sgx, 256>>>(OUTP, oh, ol, NX);
    gemm_bf16x3<1><<<ggrid, 256, GSMEM_DYN>>>(oh, ol, w1h, w1l, b1, H1, 1.0f, nullptr, nullptr);
    split_kernel<<<sgx, 256>>>(H1, hh, hl, NX);
    gemm_bf16x3<2><<<ggrid, 256, GSMEM_DYN>>>(hh, hl, w2h, w2l, b2, Y, 1.0f, x, OUTP);
}